// round 4
// baseline (speedup 1.0000x reference)
#include <cuda_runtime.h>
#include <math.h>

#define D 256
#define O 10
#define NS 64
#define R 640   // NS*O

typedef unsigned long long u64;

__device__ __forceinline__ u64 ffma2(u64 a, u64 b, u64 c) {
    asm("fma.rn.f32x2 %0, %1, %2, %0;" : "+l"(c) : "l"(a), "l"(b));
    return c;
}
__device__ __forceinline__ float2 unpack2(u64 v) {
    float2 f;
    asm("mov.b64 {%0, %1}, %2;" : "=f"(f.x), "=f"(f.y) : "l"(v));
    return f;
}

// ---------------- scratch ----------------
__device__ float d_H1[2 * NS * D];
__device__ float d_H2[2 * NS * D];
__device__ float d_G1[2 * R * D];
__device__ float d_G2[2 * R * D];
__device__ float d_C[3][NS * NS];

// ================= K1: fused forward (both layers) + G2, 4 samples/CTA ===========
__global__ __launch_bounds__(256) void k1_fwd(
    const float* __restrict__ x1, const float* __restrict__ x2,
    const float* __restrict__ W1, const float* __restrict__ b1,
    const float* __restrict__ W2, const float* __restrict__ b2,
    const float* __restrict__ W3)
{
    __shared__ __align__(16) float xT[D * 4];
    __shared__ __align__(16) float h1T[D * 4];

    const int t = threadIdx.x;
    const int s0 = blockIdx.x * 4;

#pragma unroll
    for (int s = 0; s < 4; s++) {
        int sg = s0 + s;
        const float* xr = (sg < NS) ? (x1 + sg * D) : (x2 + (sg - NS) * D);
        xT[t * 4 + s] = xr[t];
    }
    __syncthreads();

    float bb = b1[t];
    float a0 = bb, a1 = bb, a2 = bb, a3 = bb;
#pragma unroll 8
    for (int i = 0; i < D; i++) {
        float w = W1[i * D + t];
        float4 xv = *(const float4*)&xT[i * 4];
        a0 += xv.x * w; a1 += xv.y * w; a2 += xv.z * w; a3 += xv.w * w;
    }
    float h10 = tanhf(a0), h11 = tanhf(a1), h12 = tanhf(a2), h13 = tanhf(a3);
    d_H1[(s0 + 0) * D + t] = h10;
    d_H1[(s0 + 1) * D + t] = h11;
    d_H1[(s0 + 2) * D + t] = h12;
    d_H1[(s0 + 3) * D + t] = h13;
    h1T[t * 4 + 0] = h10; h1T[t * 4 + 1] = h11;
    h1T[t * 4 + 2] = h12; h1T[t * 4 + 3] = h13;
    __syncthreads();

    bb = b2[t];
    a0 = bb; a1 = bb; a2 = bb; a3 = bb;
#pragma unroll 8
    for (int i = 0; i < D; i++) {
        float w = W2[i * D + t];
        float4 hv = *(const float4*)&h1T[i * 4];
        a0 += hv.x * w; a1 += hv.y * w; a2 += hv.z * w; a3 += hv.w * w;
    }
    float h20 = tanhf(a0), h21 = tanhf(a1), h22 = tanhf(a2), h23 = tanhf(a3);
    d_H2[(s0 + 0) * D + t] = h20;
    d_H2[(s0 + 1) * D + t] = h21;
    d_H2[(s0 + 2) * D + t] = h22;
    d_H2[(s0 + 3) * D + t] = h23;
    float t20 = 1.f - h20 * h20, t21 = 1.f - h21 * h21;
    float t22 = 1.f - h22 * h22, t23 = 1.f - h23 * h23;

#pragma unroll
    for (int a = 0; a < O; a++) {
        float w3 = W3[t * O + a];
        d_G2[((s0 + 0) * O + a) * D + t] = w3 * t20;
        d_G2[((s0 + 1) * O + a) * D + t] = w3 * t21;
        d_G2[((s0 + 2) * O + a) * D + t] = w3 * t22;
        d_G2[((s0 + 3) * O + a) * D + t] = w3 * t23;
    }
}

// ================= K_dots ==========================================================
__global__ __launch_bounds__(256) void k_dots(
    const float* __restrict__ x1, const float* __restrict__ x2)
{
    __shared__ float xa[D], h1a[D], h2a[D];
    const int n = blockIdx.x;
    const int t = threadIdx.x;
    xa[t]  = x1[n * D + t];
    h1a[t] = d_H1[n * D + t];
    h2a[t] = d_H2[n * D + t];
    __syncthreads();

    const int warp = t >> 5, lane = t & 31;
#pragma unroll
    for (int mi = 0; mi < 8; mi++) {
        int m = warp * 8 + mi;
        const float* x2r = x2 + m * D;
        const float* h1r = d_H1 + (NS + m) * D;
        const float* h2r = d_H2 + (NS + m) * D;
        float s0 = 0.f, s1 = 0.f, s2 = 0.f;
#pragma unroll
        for (int k = lane; k < D; k += 32) {
            s0 += xa[k]  * x2r[k];
            s1 += h1a[k] * h1r[k];
            s2 += h2a[k] * h2r[k];
        }
#pragma unroll
        for (int off = 16; off > 0; off >>= 1) {
            s0 += __shfl_down_sync(0xffffffffu, s0, off);
            s1 += __shfl_down_sync(0xffffffffu, s1, off);
            s2 += __shfl_down_sync(0xffffffffu, s2, off);
        }
        if (lane == 0) {
            d_C[0][n * NS + m] = s0 + 1.0f;
            d_C[1][n * NS + m] = s1 + 1.0f;
            d_C[2][n * NS + m] = s2 + 1.0f;
        }
    }
}

// ---- shared GEMM machinery: 32(M)x64(N) tile, 256 threads, 2x4 micro, f32x2 -----
// Asd holds A values duplicated: A[k][r] at Asd[k][2r] and [2r+1] -> LDS.128 gives
// two broadcast-ready f32x2 operands. Bs holds B k-major.
#define GEMM_DECLS                                                             \
    __shared__ __align__(16) float Asd[32][68];                                \
    __shared__ __align__(16) float Bs[32][68];                                 \
    const int tid = threadIdx.x;                                               \
    const int ty = tid >> 4;      /* 0..15 -> rows 2ty, 2ty+1 */               \
    const int tx = tid & 15;      /* 0..15 -> cols 4tx..4tx+3 */               \
    const int ldrow = tid >> 3;   /* 0..31 */                                  \
    const int kq = tid & 7;       /* float4 k-chunk index */                   \
    float4 ra, rb0, rb1;

#define GEMM_LDG(Ap, Bp, kc) {                                                 \
    ra  = *(const float4*)&(Ap)[ldrow * D + (kc) + kq * 4];                    \
    rb0 = *(const float4*)&(Bp)[ldrow * D + (kc) + kq * 4];                    \
    rb1 = *(const float4*)&(Bp)[(32 + ldrow) * D + (kc) + kq * 4];             \
}

#define GEMM_STS() {                                                           \
    float av[4] = {ra.x, ra.y, ra.z, ra.w};                                    \
    float b0v[4] = {rb0.x, rb0.y, rb0.z, rb0.w};                               \
    float b1v[4] = {rb1.x, rb1.y, rb1.z, rb1.w};                               \
    _Pragma("unroll")                                                          \
    for (int c = 0; c < 4; c++) {                                              \
        int k = kq * 4 + c;                                                    \
        *(float2*)&Asd[k][2 * ldrow] = make_float2(av[c], av[c]);              \
        Bs[k][ldrow] = b0v[c];                                                 \
        Bs[k][32 + ldrow] = b1v[c];                                            \
    } }

#define GEMM_COMP(A00, A01, A10, A11) {                                        \
    _Pragma("unroll")                                                          \
    for (int k = 0; k < 32; k++) {                                             \
        ulonglong2 aa = *(const ulonglong2*)&Asd[k][4 * ty];                   \
        ulonglong2 bb = *(const ulonglong2*)&Bs[k][4 * tx];                    \
        A00 = ffma2(aa.x, bb.x, A00);                                          \
        A01 = ffma2(aa.x, bb.y, A01);                                          \
        A10 = ffma2(aa.y, bb.x, A10);                                          \
        A11 = ffma2(aa.y, bb.y, A11);                                          \
    } }

// ================= K2: G1 = (G2[1280,256] @ W2^T) .* (1-h1^2) =====================
// grid (4, 40), 256 threads
__global__ __launch_bounds__(256) void k2_g1(const float* __restrict__ W2)
{
    GEMM_DECLS
    const int r0 = blockIdx.y * 32;
    const int c0 = blockIdx.x * 64;
    const float* Ap = d_G2 + r0 * D;
    const float* Bp = W2 + c0 * D;

    u64 a00 = 0, a01 = 0, a10 = 0, a11 = 0;

    GEMM_LDG(Ap, Bp, 0); GEMM_STS(); __syncthreads();
    for (int st = 0; st < 8; st++) {
        if (st < 7) GEMM_LDG(Ap, Bp, (st + 1) * 32);
        GEMM_COMP(a00, a01, a10, a11);
        __syncthreads();
        if (st < 7) { GEMM_STS(); __syncthreads(); }
    }

    // epilogue: scale by (1 - h1[s, col]^2)
    u64 accs[2][2] = {{a00, a01}, {a10, a11}};
#pragma unroll
    for (int i = 0; i < 2; i++) {
        int r = r0 + 2 * ty + i;
        int s = r / 10;
        int col = c0 + 4 * tx;
        float4 hv = *(const float4*)&d_H1[s * D + col];
        float2 p0 = unpack2(accs[i][0]);
        float2 p1 = unpack2(accs[i][1]);
        float4 v;
        v.x = p0.x * (1.f - hv.x * hv.x);
        v.y = p0.y * (1.f - hv.y * hv.y);
        v.z = p1.x * (1.f - hv.z * hv.z);
        v.w = p1.y * (1.f - hv.w * hv.w);
        *(float4*)&d_G1[r * D + col] = v;
    }
}

// ================= K3: fused pair-GEMMs (both layers) + NTK combine ===============
// grid (10, 20), 256 threads. K = 512 fused (8 stages G1, 8 stages G2).
__global__ __launch_bounds__(256) void k3_pair(float* __restrict__ out)
{
    GEMM_DECLS
    const int r0 = blockIdx.y * 32;
    const int c0 = blockIdx.x * 64;

    u64 l0_00 = 0, l0_01 = 0, l0_10 = 0, l0_11 = 0;
    u64 l1_00 = 0, l1_01 = 0, l1_10 = 0, l1_11 = 0;

    const float* A0 = d_G1 + r0 * D;
    const float* B0 = d_G1 + R * D + c0 * D;
    const float* A1 = d_G2 + r0 * D;
    const float* B1 = d_G2 + R * D + c0 * D;

    GEMM_LDG(A0, B0, 0); GEMM_STS(); __syncthreads();
    for (int st = 0; st < 8; st++) {
        if (st < 7)       GEMM_LDG(A0, B0, (st + 1) * 32)
        else              GEMM_LDG(A1, B1, 0)
        GEMM_COMP(l0_00, l0_01, l0_10, l0_11);
        __syncthreads();
        GEMM_STS(); __syncthreads();
    }
    for (int st = 0; st < 8; st++) {
        if (st < 7) GEMM_LDG(A1, B1, (st + 1) * 32);
        GEMM_COMP(l1_00, l1_01, l1_10, l1_11);
        __syncthreads();
        if (st < 7) { GEMM_STS(); __syncthreads(); }
    }

    // ---- epilogue: out[n,m,a,b] = C0*P0 + C1*P1 + (a==b)*C2 ----
    u64 acc0[2][2] = {{l0_00, l0_01}, {l0_10, l0_11}};
    u64 acc1[2][2] = {{l1_00, l1_01}, {l1_10, l1_11}};
#pragma unroll
    for (int i = 0; i < 2; i++) {
        int row = r0 + 2 * ty + i;            // n*10 + a
        int n = row / 10, a = row - n * 10;
#pragma unroll
        for (int jp = 0; jp < 2; jp++) {
            float2 p0 = unpack2(acc0[i][jp]);
            float2 p1 = unpack2(acc1[i][jp]);
            float pv0[2] = {p0.x, p0.y};
            float pv1[2] = {p1.x, p1.y};
#pragma unroll
            for (int j = 0; j < 2; j++) {
                int col = c0 + 4 * tx + 2 * jp + j;   // m*10 + b
                int m = col / 10, bb = col - m * 10;
                int ci = n * NS + m;
                float v = d_C[0][ci] * pv0[j] + d_C[1][ci] * pv1[j];
                if (a == bb) v += d_C[2][ci];
                out[(n * NS + m) * 100 + a * 10 + bb] = v;
            }
        }
    }
}

// ---------------- launcher ----------------
extern "C" void kernel_launch(void* const* d_in, const int* in_sizes, int n_in,
                              void* d_out, int out_size) {
    const float* x1 = (const float*)d_in[0];
    const float* x2 = (const float*)d_in[1];
    const float* W1 = (const float*)d_in[2];
    const float* b1 = (const float*)d_in[3];
    const float* W2 = (const float*)d_in[4];
    const float* b2 = (const float*)d_in[5];
    const float* W3 = (const float*)d_in[6];
    float* out = (float*)d_out;

    k1_fwd<<<32, 256>>>(x1, x2, W1, b1, W2, b2, W3);
    k_dots<<<64, 256>>>(x1, x2);
    k2_g1<<<dim3(4, 40), 256>>>(W2);
    k3_pair<<<dim3(10, 20), 256>>>(out);
}

// round 5
// speedup vs baseline: 1.5517x; 1.5517x over previous
#include <cuda_runtime.h>
#include <math.h>

#define D 256
#define O 10
#define NS 64
#define R 640   // NS*O

// ---------------- scratch ----------------
__device__ float d_W2P[D * D];     // float4 at (k4*D + t) holds W2[t][4k4..4k4+3]
__device__ float d_H1[2 * NS * D];
__device__ float d_H2[2 * NS * D];
__device__ float d_G1[2 * R * D];
__device__ float d_G2[2 * R * D];
__device__ float d_P[2][R * R];
__device__ float d_C[3][NS * NS];

// ================= K1: W2 pack (blocks 0..63) + fused forward, 4 samples/CTA =====
__global__ __launch_bounds__(256) void k1_fwd(
    const float* __restrict__ x1, const float* __restrict__ x2,
    const float* __restrict__ W1, const float* __restrict__ b1,
    const float* __restrict__ W2, const float* __restrict__ b2,
    const float* __restrict__ W3)
{
    __shared__ __align__(16) float xT[D * 4];
    __shared__ __align__(16) float h1T[D * 4];

    const int b = blockIdx.x, t = threadIdx.x;

    if (b < 64) {
        // pack W2 rows k-major: W2P[(k4*D + tw)*4 ..] = W2[tw][4k4..4k4+3]
        int gid = b * 256 + t;
        int k4 = gid & 63, tw = gid >> 6;
        float4 v = *(const float4*)&W2[tw * D + k4 * 4];
        *(float4*)&d_W2P[(k4 * D + tw) * 4] = v;
        return;
    }

    const int s0 = (b - 64) * 4;

#pragma unroll
    for (int s = 0; s < 4; s++) {
        int sg = s0 + s;
        const float* xr = (sg < NS) ? (x1 + sg * D) : (x2 + (sg - NS) * D);
        xT[t * 4 + s] = xr[t];
    }
    __syncthreads();

    // layer 1: 4 independent sample accumulators, broadcast LDS.128 per k
    float bb = b1[t];
    float a0 = bb, a1 = bb, a2 = bb, a3 = bb;
#pragma unroll 8
    for (int i = 0; i < D; i++) {
        float w = W1[i * D + t];
        float4 xv = *(const float4*)&xT[i * 4];
        a0 += xv.x * w; a1 += xv.y * w; a2 += xv.z * w; a3 += xv.w * w;
    }
    float h10 = tanhf(a0), h11 = tanhf(a1), h12 = tanhf(a2), h13 = tanhf(a3);
    d_H1[(s0 + 0) * D + t] = h10;
    d_H1[(s0 + 1) * D + t] = h11;
    d_H1[(s0 + 2) * D + t] = h12;
    d_H1[(s0 + 3) * D + t] = h13;
    h1T[t * 4 + 0] = h10; h1T[t * 4 + 1] = h11;
    h1T[t * 4 + 2] = h12; h1T[t * 4 + 3] = h13;
    __syncthreads();

    // layer 2
    bb = b2[t];
    a0 = bb; a1 = bb; a2 = bb; a3 = bb;
#pragma unroll 8
    for (int i = 0; i < D; i++) {
        float w = W2[i * D + t];
        float4 hv = *(const float4*)&h1T[i * 4];
        a0 += hv.x * w; a1 += hv.y * w; a2 += hv.z * w; a3 += hv.w * w;
    }
    float h20 = tanhf(a0), h21 = tanhf(a1), h22 = tanhf(a2), h23 = tanhf(a3);
    d_H2[(s0 + 0) * D + t] = h20;
    d_H2[(s0 + 1) * D + t] = h21;
    d_H2[(s0 + 2) * D + t] = h22;
    d_H2[(s0 + 3) * D + t] = h23;
    float t20 = 1.f - h20 * h20, t21 = 1.f - h21 * h21;
    float t22 = 1.f - h22 * h22, t23 = 1.f - h23 * h23;

#pragma unroll
    for (int a = 0; a < O; a++) {
        float w3 = W3[t * O + a];
        d_G2[((s0 + 0) * O + a) * D + t] = w3 * t20;
        d_G2[((s0 + 1) * O + a) * D + t] = w3 * t21;
        d_G2[((s0 + 2) * O + a) * D + t] = w3 * t22;
        d_G2[((s0 + 3) * O + a) * D + t] = w3 * t23;
    }
}

// ================= K2: G1 backward (blocks 0..255) + pairwise dots (256..319) =====
// (round-2 version, measured fast)
__global__ __launch_bounds__(256) void k2_bwd_dots(
    const float* __restrict__ x1, const float* __restrict__ x2)
{
    __shared__ float sm[5 * D];
    const int b = blockIdx.x, t = threadIdx.x;

    if (b < 256) {
        const int s = b >> 1, half = b & 1;
#pragma unroll
        for (int j = 0; j < 5; j++)
            sm[j * D + t] = d_G2[(s * O + half * 5 + j) * D + t];
        float h1 = d_H1[s * D + t];
        float t1 = 1.0f - h1 * h1;
        __syncthreads();

        float a0 = 0.f, a1 = 0.f, a2 = 0.f, a3 = 0.f, a4 = 0.f;
#pragma unroll 4
        for (int k4 = 0; k4 < 64; k4++) {
            float4 w  = *(const float4*)&d_W2P[(k4 * D + t) * 4];
            float4 g0 = *(const float4*)&sm[0 * D + k4 * 4];
            float4 g1 = *(const float4*)&sm[1 * D + k4 * 4];
            float4 g2 = *(const float4*)&sm[2 * D + k4 * 4];
            float4 g3 = *(const float4*)&sm[3 * D + k4 * 4];
            float4 g4 = *(const float4*)&sm[4 * D + k4 * 4];
            a0 += w.x * g0.x + w.y * g0.y + w.z * g0.z + w.w * g0.w;
            a1 += w.x * g1.x + w.y * g1.y + w.z * g1.z + w.w * g1.w;
            a2 += w.x * g2.x + w.y * g2.y + w.z * g2.z + w.w * g2.w;
            a3 += w.x * g3.x + w.y * g3.y + w.z * g3.z + w.w * g3.w;
            a4 += w.x * g4.x + w.y * g4.y + w.z * g4.z + w.w * g4.w;
        }
        const int base = (s * O + half * 5) * D + t;
        d_G1[base + 0 * D] = t1 * a0;
        d_G1[base + 1 * D] = t1 * a1;
        d_G1[base + 2 * D] = t1 * a2;
        d_G1[base + 3 * D] = t1 * a3;
        d_G1[base + 4 * D] = t1 * a4;
        return;
    }

    const int n = b - 256;
    float* xa  = sm;
    float* h1a = sm + D;
    float* h2a = sm + 2 * D;
    xa[t]  = x1[n * D + t];
    h1a[t] = d_H1[n * D + t];
    h2a[t] = d_H2[n * D + t];
    __syncthreads();

    const int warp = t >> 5, lane = t & 31;
#pragma unroll
    for (int mi = 0; mi < 8; mi++) {
        int m = warp * 8 + mi;
        const float* x2r = x2 + m * D;
        const float* h1r = d_H1 + (NS + m) * D;
        const float* h2r = d_H2 + (NS + m) * D;
        float s0 = 0.f, s1 = 0.f, s2 = 0.f;
#pragma unroll
        for (int k = lane; k < D; k += 32) {
            s0 += xa[k]  * x2r[k];
            s1 += h1a[k] * h1r[k];
            s2 += h2a[k] * h2r[k];
        }
#pragma unroll
        for (int off = 16; off > 0; off >>= 1) {
            s0 += __shfl_down_sync(0xffffffffu, s0, off);
            s1 += __shfl_down_sync(0xffffffffu, s1, off);
            s2 += __shfl_down_sync(0xffffffffu, s2, off);
        }
        if (lane == 0) {
            d_C[0][n * NS + m] = s0 + 1.0f;
            d_C[1][n * NS + m] = s1 + 1.0f;
            d_C[2][n * NS + m] = s2 + 1.0f;
        }
    }
}

// ================= K3: P_l = G_l1[640,256] @ G_l2[640,256]^T  (double-buffered) ====
// 64x64 tile, 256 threads, 4x4 micro, 16-deep K chunks, grid (10,10,2)
__global__ __launch_bounds__(256) void gemm64() {
    const int layer = blockIdx.z;
    const float* G = (layer == 0) ? d_G1 : d_G2;
    const float* A = G;
    const float* B = G + R * D;
    float* P = d_P[layer];

    __shared__ __align__(16) float As[2][16][68];
    __shared__ __align__(16) float Bs[2][16][68];

    const int tid = threadIdx.x;
    const int tx = tid & 15, ty = tid >> 4;
    const int r0 = blockIdx.y * 64, c0 = blockIdx.x * 64;
    const int lrow = tid >> 2;          // 0..63
    const int lk   = (tid & 3) * 4;     // 0,4,8,12

    float4 a4, b4;
    float acc[4][4] = {};

#define G64_LDG(kc) {                                                         \
    a4 = *(const float4*)&A[(r0 + lrow) * D + (kc) + lk];                     \
    b4 = *(const float4*)&B[(c0 + lrow) * D + (kc) + lk];                     \
}
#define G64_STS(buf) {                                                        \
    As[buf][lk + 0][lrow] = a4.x; As[buf][lk + 1][lrow] = a4.y;               \
    As[buf][lk + 2][lrow] = a4.z; As[buf][lk + 3][lrow] = a4.w;               \
    Bs[buf][lk + 0][lrow] = b4.x; Bs[buf][lk + 1][lrow] = b4.y;               \
    Bs[buf][lk + 2][lrow] = b4.z; Bs[buf][lk + 3][lrow] = b4.w;               \
}

    G64_LDG(0); G64_STS(0); __syncthreads();

#pragma unroll 1
    for (int st = 0; st < 16; st++) {
        const int cur = st & 1;
        if (st < 15) G64_LDG((st + 1) * 16);
#pragma unroll
        for (int k = 0; k < 16; k++) {
            float4 av = *(const float4*)&As[cur][k][ty * 4];
            float4 bv = *(const float4*)&Bs[cur][k][tx * 4];
            float a[4] = {av.x, av.y, av.z, av.w};
            float bb[4] = {bv.x, bv.y, bv.z, bv.w};
#pragma unroll
            for (int i = 0; i < 4; i++)
#pragma unroll
                for (int j = 0; j < 4; j++)
                    acc[i][j] += a[i] * bb[j];
        }
        if (st < 15) { G64_STS(cur ^ 1); __syncthreads(); }
    }
#undef G64_LDG
#undef G64_STS

#pragma unroll
    for (int i = 0; i < 4; i++) {
        float4 v = make_float4(acc[i][0], acc[i][1], acc[i][2], acc[i][3]);
        *(float4*)&P[(r0 + ty * 4 + i) * R + c0 + tx * 4] = v;
    }
}

// ================= K4: combine ====================================================
__global__ __launch_bounds__(256) void combine_kernel(float* __restrict__ out) {
    int idx = blockIdx.x * 256 + threadIdx.x;
    if (idx >= NS * NS * O * O) return;
    int n  = idx / (NS * O * O);
    int r  = idx % (NS * O * O);
    int m  = r / (O * O);
    int ab = r % (O * O);
    int a = ab / O, b = ab % O;
    int pidx = (n * O + a) * R + (m * O + b);
    int cidx = n * NS + m;
    float v = d_C[0][cidx] * d_P[0][pidx]
            + d_C[1][cidx] * d_P[1][pidx];
    if (a == b) v += d_C[2][cidx];
    out[idx] = v;
}

// ---------------- launcher ----------------
extern "C" void kernel_launch(void* const* d_in, const int* in_sizes, int n_in,
                              void* d_out, int out_size) {
    const float* x1 = (const float*)d_in[0];
    const float* x2 = (const float*)d_in[1];
    const float* W1 = (const float*)d_in[2];
    const float* b1 = (const float*)d_in[3];
    const float* W2 = (const float*)d_in[4];
    const float* b2 = (const float*)d_in[5];
    const float* W3 = (const float*)d_in[6];
    float* out = (float*)d_out;

    k1_fwd<<<96, 256>>>(x1, x2, W1, b1, W2, b2, W3);
    k2_bwd_dots<<<320, 256>>>(x1, x2);
    gemm64<<<dim3(10, 10, 2), 256>>>();
    combine_kernel<<<(NS * NS * O * O + 255) / 256, 256>>>(out);
}